// round 8
// baseline (speedup 1.0000x reference)
#include <cuda_runtime.h>
#include <math.h>
#include <stdint.h>

#define LNUM   102
#define LSTART 100
#define KDIM   104            // 13 k-tiles of 8 (cols 102,103 zero-pad)
#define NKT    13
#define NT     128
#define G      8              // sequences per block = MMA N
#define MAXB   1024
#define BSTR   12             // q_sh row stride in floats
#define SCALE  4.0f

__device__ int g_perm[MAXB];

// ---------- LPT pre-sort: order batches by descending length ----------
__global__ void sort_kernel(const int* __restrict__ lens, int B) {
    __shared__ int keys[MAXB];
    const int tid = threadIdx.x;
    for (int i = tid; i < MAXB; i += blockDim.x)
        keys[i] = (i < B) ? ((lens[i] << 10) | (MAXB - 1 - i)) : -1;
    __syncthreads();
    for (int k = 2; k <= MAXB; k <<= 1) {
        for (int j = k >> 1; j > 0; j >>= 1) {
            for (int i = tid; i < MAXB; i += blockDim.x) {
                int ixj = i ^ j;
                if (ixj > i) {
                    int a = keys[i], c = keys[ixj];
                    bool seg = ((i & k) == 0);   // descending
                    if (seg ? (a < c) : (a > c)) { keys[i] = c; keys[ixj] = a; }
                }
            }
            __syncthreads();
        }
    }
    for (int i = tid; i < B; i += blockDim.x)
        g_perm[i] = (MAXB - 1) - (keys[i] & (MAXB - 1));
}

// m16n8k8 tf32 MMA, D += A*B
__device__ __forceinline__ void mma8(float* d, const uint32_t* a,
                                     uint32_t b0, uint32_t b1) {
    asm volatile(
        "mma.sync.aligned.m16n8k8.row.col.f32.tf32.tf32.f32 "
        "{%0,%1,%2,%3}, {%4,%5,%6,%7}, {%8,%9}, {%0,%1,%2,%3};"
        : "+f"(d[0]), "+f"(d[1]), "+f"(d[2]), "+f"(d[3])
        : "r"(a[0]), "r"(a[1]), "r"(a[2]), "r"(a[3]), "r"(b0), "r"(b1));
}

__device__ __forceinline__ uint32_t to_tf32(float x) {
    uint32_t u;
    asm("cvt.rna.tf32.f32 %0, %1;" : "=r"(u) : "f"(x));
    return u;
}

// ---------- CRF forward: 8 sequences/block via m16n8k8 tf32 MMA ----------
__global__ __launch_bounds__(NT)
void crf_mma_kernel(const float* __restrict__ logits,
                    const float* __restrict__ trans,
                    const int*   __restrict__ lens,
                    float* __restrict__ out,
                    int T, int B)
{
    const int tid = threadIdx.x;
    const int w  = tid >> 5;
    const int l  = tid & 31;
    const int lq = l >> 2;          // groupID   (0..7) -> B col / D row
    const int lr = l & 3;           // tid-in-group (0..3)
    const int g0 = 2 * lr, g1 = g0 + 1;

    __shared__ float q_sh[2][KDIM][BSTR];
    __shared__ int   smax[2][8];
    __shared__ float wsum[4][8];
    __shared__ float sC[8];
    __shared__ int   sh_bs[8], sh_len[8];

    // rows owned by this thread: tile0 -> R[0],R[1]; tile1 -> R[2],R[3]
    int R[4];
    R[0] = 32 * w + lq; R[1] = R[0] + 8; R[2] = R[0] + 16; R[3] = R[0] + 24;

    // group setup
    if (tid < G) {
        int idx = G * blockIdx.x + tid;
        int bsv = g_perm[(idx < B) ? idx : (B - 1)];
        sh_bs[tid] = bsv;
        int ln = lens[bsv]; if (ln > T) ln = T; if (ln < 0) ln = 0;
        sh_len[tid] = ln;
    }
    if (tid < 16) ((int*)smax)[tid] = 0;

    // A fragments: E[r][k] = exp(trans[r,k]); rows>=102 or cols>=102 -> 0
    uint32_t A[2][NKT][4];
    #pragma unroll
    for (int i = 0; i < 2; ++i) {
        const int r0 = R[2 * i], r1 = R[2 * i + 1];
        #pragma unroll
        for (int kt = 0; kt < NKT; ++kt) {
            const int c0 = 8 * kt + lr, c1 = c0 + 4;
            float e00 = (r0 < LNUM && c0 < LNUM) ? __expf(trans[r0 * LNUM + c0]) : 0.f;
            float e10 = (r1 < LNUM && c0 < LNUM) ? __expf(trans[r1 * LNUM + c0]) : 0.f;
            float e01 = (r0 < LNUM && c1 < LNUM) ? __expf(trans[r0 * LNUM + c1]) : 0.f;
            float e11 = (r1 < LNUM && c1 < LNUM) ? __expf(trans[r1 * LNUM + c1]) : 0.f;
            A[i][kt][0] = to_tf32(e00); A[i][kt][1] = to_tf32(e10);
            A[i][kt][2] = to_tf32(e01); A[i][kt][3] = to_tf32(e11);
        }
    }

    float estop[4];
    #pragma unroll
    for (int i = 0; i < 4; ++i)
        estop[i] = (R[i] < LNUM) ? __expf(trans[(LNUM - 1) * LNUM + R[i]]) : 0.f;

    // init q = exp(alpha0): 1 at start label
    float qold[4][2];
    #pragma unroll
    for (int i = 0; i < 4; ++i) {
        qold[i][0] = (R[i] == LSTART) ? 1.f : 0.f;
        qold[i][1] = qold[i][0];
        if (R[i] < KDIM)
            *(float2*)&q_sh[0][R[i]][g0] = make_float2(qold[i][0], qold[i][1]);
    }
    __syncthreads();

    const int len0 = sh_len[g0], len1 = sh_len[g1];
    int mlen = 0;
    #pragma unroll
    for (int g = 0; g < 8; ++g) mlen = max(mlen, sh_len[g]);

    const float* p0 = logits + (size_t)sh_bs[g0] * T * LNUM;
    const float* p1 = logits + (size_t)sh_bs[g1] * T * LNUM;

    float C0 = 0.f, C1 = 0.f;

    // depth-2 logit prefetch, parity buffers
    float lgv[2][4][2];
    #pragma unroll
    for (int i = 0; i < 4; ++i) {
        lgv[0][i][0] = lgv[0][i][1] = lgv[1][i][0] = lgv[1][i][1] = 0.f;
        if (R[i] < LNUM) {
            if (0 < mlen) { lgv[0][i][0] = p0[R[i]];        lgv[0][i][1] = p1[R[i]]; }
            if (1 < mlen) { lgv[1][i][0] = p0[LNUM + R[i]]; lgv[1][i][1] = p1[LNUM + R[i]]; }
        }
    }

    #pragma unroll 2
    for (int t = 0; t < mlen; ++t) {
        const int pb = t & 1;

        // el = exp(logit - SCALE); overlaps the MMA chain
        float el[4][2];
        #pragma unroll
        for (int i = 0; i < 4; ++i) {
            el[i][0] = __expf(lgv[pb][i][0] - SCALE);
            el[i][1] = __expf(lgv[pb][i][1] - SCALE);
        }

        // prefetch logits for t+2 into the freed parity buffer
        const int tp = t + 2;
        if (tp < mlen) {
            const size_t off = (size_t)tp * LNUM;
            #pragma unroll
            for (int i = 0; i < 4; ++i)
                if (R[i] < LNUM) {
                    lgv[pb][i][0] = p0[off + R[i]];
                    lgv[pb][i][1] = p1[off + R[i]];
                }
        }

        // renorm: apply scale measured at t-1 (every 16 steps)
        float s0 = 1.f, s1 = 1.f;
        bool do_scale = ((t & 15) == 0) && (t > 0);
        if (do_scale) {
            const int bi = ((t - 1) >> 4) & 1;
            float M0 = __int_as_float(smax[bi][g0]); if (!(M0 > 1e-30f)) M0 = 1.f;
            float M1 = __int_as_float(smax[bi][g1]); if (!(M1 > 1e-30f)) M1 = 1.f;
            s0 = __fdividef(1.f, M0); C0 += __logf(M0);
            s1 = __fdividef(1.f, M1); C1 += __logf(M1);
        }
        if ((t & 15) == 8 && tid < 8)        // reset the other max buffer
            smax[((t >> 4) + 1) & 1][tid] = 0;

        // Y = E * Q : 2 m-tiles x 13 k-tiles, split-K (depth 7+6)
        float acc[2][2][4] = {};
        {
            const float (*qs)[BSTR] = q_sh[t & 1];
            #pragma unroll
            for (int kt = 0; kt < NKT; ++kt) {
                const int kr = 8 * kt + lr;
                const uint32_t b0 = __float_as_uint(qs[kr][lq]);
                const uint32_t b1 = __float_as_uint(qs[kr + 4][lq]);
                const int ks = (kt >= 7);
                mma8(acc[0][ks], A[0][kt], b0, b1);
                mma8(acc[1][ks], A[1][kt], b0, b1);
            }
        }

        // q' = el * y  (frozen cols keep q); apply renorm scale
        const bool v0 = (t < len0), v1 = (t < len1);
        float qn[4][2];
        // D frag mapping: c0=(R[2i],g0) c1=(R[2i],g1) c2=(R[2i+1],g0) c3=(R[2i+1],g1)
        qn[0][0] = v0 ? el[0][0] * (acc[0][0][0] + acc[0][1][0]) : qold[0][0];
        qn[0][1] = v1 ? el[0][1] * (acc[0][0][1] + acc[0][1][1]) : qold[0][1];
        qn[1][0] = v0 ? el[1][0] * (acc[0][0][2] + acc[0][1][2]) : qold[1][0];
        qn[1][1] = v1 ? el[1][1] * (acc[0][0][3] + acc[0][1][3]) : qold[1][1];
        qn[2][0] = v0 ? el[2][0] * (acc[1][0][0] + acc[1][1][0]) : qold[2][0];
        qn[2][1] = v1 ? el[2][1] * (acc[1][0][1] + acc[1][1][1]) : qold[2][1];
        qn[3][0] = v0 ? el[3][0] * (acc[1][0][2] + acc[1][1][2]) : qold[3][0];
        qn[3][1] = v1 ? el[3][1] * (acc[1][0][3] + acc[1][1][3]) : qold[3][1];
        if (do_scale) {
            #pragma unroll
            for (int i = 0; i < 4; ++i) { qn[i][0] *= s0; qn[i][1] *= s1; }
        }
        #pragma unroll
        for (int i = 0; i < 4; ++i) { qold[i][0] = qn[i][0]; qold[i][1] = qn[i][1]; }

        // measure per-column max every 16th step (order-independent atomicMax)
        if ((t & 15) == 15) {
            float m0 = fmaxf(fmaxf(qn[0][0], qn[1][0]), fmaxf(qn[2][0], qn[3][0]));
            float m1 = fmaxf(fmaxf(qn[0][1], qn[1][1]), fmaxf(qn[2][1], qn[3][1]));
            #pragma unroll
            for (int off = 16; off >= 4; off >>= 1) {
                m0 = fmaxf(m0, __shfl_xor_sync(0xffffffffu, m0, off));
                m1 = fmaxf(m1, __shfl_xor_sync(0xffffffffu, m1, off));
            }
            if (l < 4) {
                const int bi = (t >> 4) & 1;
                atomicMax(&smax[bi][g0], __float_as_int(m0));
                atomicMax(&smax[bi][g1], __float_as_int(m1));
            }
        }

        // publish q' for next step
        #pragma unroll
        for (int i = 0; i < 4; ++i)
            if (R[i] < KDIM)
                *(float2*)&q_sh[(t + 1) & 1][R[i]][g0] =
                    make_float2(qn[i][0], qn[i][1]);
        __syncthreads();
    }

    // out[g] = C + SCALE*len + log( sum_j q[j,g] * exp(trans[stop,j]) )
    float part0 = 0.f, part1 = 0.f;
    #pragma unroll
    for (int i = 0; i < 4; ++i) {
        part0 += qold[i][0] * estop[i];
        part1 += qold[i][1] * estop[i];
    }
    #pragma unroll
    for (int off = 16; off >= 4; off >>= 1) {
        part0 += __shfl_xor_sync(0xffffffffu, part0, off);
        part1 += __shfl_xor_sync(0xffffffffu, part1, off);
    }
    if (l < 4) {
        wsum[w][g0] = part0; wsum[w][g1] = part1;
        if (w == 0) { sC[g0] = C0; sC[g1] = C1; }
    }
    __syncthreads();
    if (tid < 8) {
        const int idx = G * blockIdx.x + tid;
        if (idx < B) {
            float s = (wsum[0][tid] + wsum[1][tid]) + (wsum[2][tid] + wsum[3][tid]);
            out[sh_bs[tid]] = sC[tid] + SCALE * (float)sh_len[tid] + __logf(s);
        }
    }
}

extern "C" void kernel_launch(void* const* d_in, const int* in_sizes, int n_in,
                              void* d_out, int out_size)
{
    const float* logits = (const float*)d_in[0];   // [B, T, L] f32
    const float* trans  = (const float*)d_in[1];   // [L, L]    f32
    const int*   lens   = (const int*)d_in[2];     // [B]       i32
    float*       out    = (float*)d_out;           // [B]       f32

    const int B = in_sizes[2];
    const int T = in_sizes[0] / (B * LNUM);
    const int nblk = (B + G - 1) / G;

    sort_kernel<<<1, MAXB>>>(lens, B);
    crf_mma_kernel<<<nblk, NT>>>(logits, trans, lens, out, T, B);
}

// round 9
// speedup vs baseline: 2.8072x; 2.8072x over previous
#include <cuda_runtime.h>
#include <math.h>

#define LNUM   102
#define LSTART 100
#define LPAD   104
#define NT     128
#define MAXB   1024
#define SCALE  4.0f

__device__ int   g_perm[MAXB];
__device__ float g_vecF[MAXB][LPAD];
__device__ float g_vecB[MAXB][LPAD];
__device__ float g_CF[MAXB];
__device__ float g_CB[MAXB];

typedef unsigned long long ull;

// ---------- packed f32x2 helpers ----------
__device__ __forceinline__ void fma2(ull& d, ull a, ull b) {
    asm("fma.rn.f32x2 %0, %1, %2, %0;" : "+l"(d) : "l"(a), "l"(b));
}
__device__ __forceinline__ ull mul2(ull a, ull b) {
    ull r; asm("mul.rn.f32x2 %0, %1, %2;" : "=l"(r) : "l"(a), "l"(b)); return r;
}
__device__ __forceinline__ ull add2(ull a, ull b) {
    ull r; asm("add.rn.f32x2 %0, %1, %2;" : "=l"(r) : "l"(a), "l"(b)); return r;
}
__device__ __forceinline__ float2 unpack2(ull u) {
    float2 f; asm("mov.b64 {%0, %1}, %2;" : "=f"(f.x), "=f"(f.y) : "l"(u)); return f;
}
__device__ __forceinline__ ull pack2(float x, float y) {
    ull u; asm("mov.b64 %0, {%1, %2};" : "=l"(u) : "f"(x), "f"(y)); return u;
}

// ---------- LPT pre-sort: order batches by descending length ----------
__global__ void sort_kernel(const int* __restrict__ lens, int B) {
    __shared__ int keys[MAXB];
    const int tid = threadIdx.x;
    for (int i = tid; i < MAXB; i += blockDim.x)
        keys[i] = (i < B) ? ((lens[i] << 10) | (MAXB - 1 - i)) : -1;
    __syncthreads();
    for (int k = 2; k <= MAXB; k <<= 1) {
        for (int j = k >> 1; j > 0; j >>= 1) {
            for (int i = tid; i < MAXB; i += blockDim.x) {
                int ixj = i ^ j;
                if (ixj > i) {
                    int a = keys[i], c = keys[ixj];
                    bool seg = ((i & k) == 0);   // descending
                    if (seg ? (a < c) : (a > c)) { keys[i] = c; keys[ixj] = a; }
                }
            }
            __syncthreads();
        }
    }
    for (int i = tid; i < B; i += blockDim.x)
        g_perm[i] = (MAXB - 1) - (keys[i] & (MAXB - 1));
}

// ---------- half-chain kernel: forward (E) or backward (E^T) ----------
__global__ __launch_bounds__(NT, 3)
void crf_half_kernel(const float* __restrict__ logits,
                     const float* __restrict__ trans,
                     const int*   __restrict__ lens,
                     int T)
{
    const int  j    = threadIdx.x;
    const int  rank = blockIdx.x >> 1;
    const bool bwd  = (blockIdx.x & 1) != 0;
    const int  b    = g_perm[rank];

    __shared__ __align__(16) float q_sh[2][LPAD];

    int len = lens[b];
    if (len > T) len = T;
    if (len < 0) len = 0;
    const int m  = len >> 1;
    const int n  = bwd ? (len - m) : m;       // steps this half runs
    const int nv = bwd ? (n - 1) : n;         // # valid logit reads in-loop

    // E fragment: fwd rows of E, bwd rows of E^T. 52 packed pairs (pads = 0).
    ull E2[52];
    #pragma unroll
    for (int mm = 0; mm < 52; ++mm) {
        float a = 0.f, c = 0.f;
        const int k = 2 * mm;
        if (j < LNUM) {
            if (!bwd) {
                const float* tr = trans + (size_t)j * LNUM;
                if (k + 0 < LNUM) a = __expf(tr[k + 0]);
                if (k + 1 < LNUM) c = __expf(tr[k + 1]);
            } else {
                if (k + 0 < LNUM) a = __expf(trans[(size_t)(k + 0) * LNUM + j]);
                if (k + 1 < LNUM) c = __expf(trans[(size_t)(k + 1) * LNUM + j]);
            }
        }
        E2[mm] = pack2(a, c);
    }

    const float* lg = logits + (size_t)b * T * LNUM;

    // init vector
    float q;
    if (!bwd) {
        q = (j == LSTART) ? 1.f : 0.f;
    } else {
        float vstop = (j < LNUM) ? __expf(trans[(size_t)(LNUM - 1) * LNUM + j]) : 0.f;
        if (len > 0) {
            float lgl = (j < LNUM) ? lg[(size_t)(len - 1) * LNUM + j] : SCALE;
            q = __expf(lgl - SCALE) * vstop;
        } else {
            q = vstop;
        }
    }
    if (j < LPAD) { q_sh[0][j] = q; q_sh[1][j] = 0.f; }

    // logit addressing: step s reads row (fwd: s) / (bwd: len-2-s)
    const ptrdiff_t strd  = bwd ? -(ptrdiff_t)LNUM : (ptrdiff_t)LNUM;
    const ptrdiff_t row0  = bwd ? (ptrdiff_t)(len - 2) * LNUM : 0;
    const float* lgcol = lg + row0 + j;

    float C = 0.f;

    // depth-4 register logit pipeline
    float lgq[4];
    #pragma unroll
    for (int u = 0; u < 4; ++u)
        lgq[u] = (u < nv && j < LNUM) ? lgcol[strd * u] : SCALE;

    __syncthreads();

    for (int tc = 0; tc < n; tc += 4) {
        // prefetch next chunk (MLP=4)
        float lgn[4];
        #pragma unroll
        for (int u = 0; u < 4; ++u) {
            const int sl = tc + 4 + u;
            lgn[u] = (sl < nv && j < LNUM) ? lgcol[strd * sl] : SCALE;
        }

        #pragma unroll
        for (int u = 0; u < 4; ++u) {
            const int t = tc + u;
            if (t >= n) break;                  // uniform across block

            const float el = __expf(lgq[u] - SCALE);

            const bool do_max = ((t & 15) == 0) && (t > 0);

            // y[j] = sum_k E[j,k] * q[k] — 26 LDS.128 + 52 FMA2
            const ulonglong2* ps =
                reinterpret_cast<const ulonglong2*>(q_sh[t & 1]);
            ulonglong2 v0 = ps[0];
            ulonglong2 v1 = ps[1];
            ull a0 = mul2(E2[0], v0.x);
            ull a1 = mul2(E2[1], v0.y);
            ull a2 = mul2(E2[2], v1.x);
            ull a3 = mul2(E2[3], v1.y);
            float m0 = 0.f, m1 = 0.f;
            if (do_max) {
                float2 fx = unpack2(v0.x), fy = unpack2(v0.y);
                float2 gx = unpack2(v1.x), gy = unpack2(v1.y);
                m0 = fmaxf(fmaxf(fx.x, fx.y), fmaxf(gx.x, gx.y));
                m1 = fmaxf(fmaxf(fy.x, fy.y), fmaxf(gy.x, gy.y));
            }
            #pragma unroll
            for (int mm = 2; mm < 26; ++mm) {
                ulonglong2 v = ps[mm];
                if (mm & 1) { fma2(a2, E2[2 * mm], v.x); fma2(a3, E2[2 * mm + 1], v.y); }
                else        { fma2(a0, E2[2 * mm], v.x); fma2(a1, E2[2 * mm + 1], v.y); }
                if (do_max) {
                    float2 fx = unpack2(v.x), fy = unpack2(v.y);
                    m0 = fmaxf(m0, fmaxf(fx.x, fx.y));
                    m1 = fmaxf(m1, fmaxf(fy.x, fy.y));
                }
            }
            float2 fs = unpack2(add2(add2(a0, a1), add2(a2, a3)));
            float y = fs.x + fs.y;

            if (do_max) {                       // uniform exact renorm every 16 steps
                const float M = fmaxf(fmaxf(m0, m1), 1e-30f);
                y *= __fdividef(1.f, M);
                C += __logf(M);
            }

            q = el * y;                         // pads: E2=0 -> y=0 -> q=0
            if (j < LPAD) q_sh[(t + 1) & 1][j] = q;
            __syncthreads();
        }

        #pragma unroll
        for (int u = 0; u < 4; ++u) lgq[u] = lgn[u];
    }

    // publish this half's vector + scale constant
    if (j < LPAD) {
        if (!bwd) g_vecF[b][j] = q;
        else      g_vecB[b][j] = q;
    }
    if (j == 0) {
        const float Ctot = C + SCALE * (float)n;
        if (!bwd) g_CF[b] = Ctot;
        else      g_CB[b] = Ctot;
    }
}

// ---------- combine: out[b] = CF + CB + log( f . g ) ----------
__global__ void combine_kernel(float* __restrict__ out, int B)
{
    const int warp = (blockIdx.x * blockDim.x + threadIdx.x) >> 5;
    const int l    = threadIdx.x & 31;
    if (warp >= B) return;

    double s = 0.0;
    for (int k = l; k < LPAD; k += 32)
        s += (double)g_vecF[warp][k] * (double)g_vecB[warp][k];
    #pragma unroll
    for (int o = 16; o; o >>= 1)
        s += __shfl_xor_sync(0xffffffffu, s, o);
    if (l == 0)
        out[warp] = g_CF[warp] + g_CB[warp] + (float)log(s);
}

extern "C" void kernel_launch(void* const* d_in, const int* in_sizes, int n_in,
                              void* d_out, int out_size)
{
    const float* logits = (const float*)d_in[0];   // [B, T, L] f32
    const float* trans  = (const float*)d_in[1];   // [L, L]    f32
    const int*   lens   = (const int*)d_in[2];     // [B]       i32
    float*       out    = (float*)d_out;           // [B]       f32

    const int B = in_sizes[2];
    const int T = in_sizes[0] / (B * LNUM);

    sort_kernel<<<1, MAXB>>>(lens, B);
    crf_half_kernel<<<2 * B, NT>>>(logits, trans, lens, T);
    combine_kernel<<<(B * 32 + NT - 1) / NT, NT>>>(out, B);
}

// round 10
// speedup vs baseline: 3.7819x; 1.3472x over previous
#include <cuda_runtime.h>
#include <cuda_bf16.h>
#include <math.h>

#define LNUM   102
#define LSTART 100
#define LPAD   104
#define NT     128
#define MAXB   1024
#define SCALE  4.0f

__device__ int   g_perm[MAXB];
__device__ float g_vecF[MAXB][LPAD];
__device__ float g_vecB[MAXB][LPAD];
__device__ float g_CF[MAXB];
__device__ float g_CB[MAXB];

typedef __nv_bfloat162 bf2;

// ---------- counting sort (descending length) -> g_perm ----------
__global__ void sort_kernel(const int* __restrict__ lens, int B, int T) {
    __shared__ int hist[513];
    __shared__ int scan[513];
    __shared__ int off[513];
    const int tid = threadIdx.x;          // 1024 threads
    if (tid < 513) hist[tid] = 0;
    __syncthreads();
    int myLen = 0;
    if (tid < B) {
        myLen = lens[tid];
        if (myLen < 0) myLen = 0;
        if (myLen > T) myLen = T;
        if (myLen > 512) myLen = 512;
        atomicAdd(&hist[myLen], 1);
    }
    __syncthreads();
    if (tid < 513) scan[tid] = hist[512 - tid];   // reversed for suffix sum
    __syncthreads();
    for (int d = 1; d < 513; d <<= 1) {           // inclusive Hillis-Steele
        int v = 0;
        if (tid < 513) { v = scan[tid]; if (tid >= d) v += scan[tid - d]; }
        __syncthreads();
        if (tid < 513) scan[tid] = v;
        __syncthreads();
    }
    // off[v] = #elements with length > v  (start of value-v run, descending)
    if (tid < 513) off[tid] = scan[512 - tid] - hist[tid];
    __syncthreads();
    if (tid < B) {
        int pos = atomicAdd(&off[myLen], 1);
        g_perm[pos] = tid;
    }
}

// ---------- half-chain kernel: forward (E) or backward (E^T), bf16 engine ----------
__global__ __launch_bounds__(NT, 4)
void crf_half_kernel(const float* __restrict__ logits,
                     const float* __restrict__ trans,
                     const int*   __restrict__ lens,
                     int T)
{
    const int  j    = threadIdx.x;
    const int  rank = blockIdx.x >> 1;
    const bool bwd  = (blockIdx.x & 1) != 0;
    const int  b    = g_perm[rank];

    __shared__ __align__(16) __nv_bfloat16 q_sh[2][LPAD];

    int len = lens[b];
    if (len > T) len = T;
    if (len < 0) len = 0;
    const int m  = len >> 1;
    const int n  = bwd ? (len - m) : m;       // steps this half runs
    const int nv = bwd ? (n - 1) : n;         // # valid logit reads in-loop

    // E fragment: fwd rows of E, bwd rows of E^T — 52 bf16x2 (pads = 0)
    bf2 E2[52];
    #pragma unroll
    for (int mm = 0; mm < 52; ++mm) {
        float a = 0.f, c = 0.f;
        const int k = 2 * mm;
        if (j < LNUM) {
            if (!bwd) {
                const float* tr = trans + (size_t)j * LNUM;
                if (k + 0 < LNUM) a = __expf(tr[k + 0]);
                if (k + 1 < LNUM) c = __expf(tr[k + 1]);
            } else {
                if (k + 0 < LNUM) a = __expf(trans[(size_t)(k + 0) * LNUM + j]);
                if (k + 1 < LNUM) c = __expf(trans[(size_t)(k + 1) * LNUM + j]);
            }
        }
        E2[mm] = __floats2bfloat162_rn(a, c);   // (x=k, y=k+1)
    }

    const float* lg = logits + (size_t)b * T * LNUM;

    // init vector
    float q;
    if (!bwd) {
        q = (j == LSTART) ? 1.f : 0.f;
    } else {
        float vstop = (j < LNUM) ? __expf(trans[(size_t)(LNUM - 1) * LNUM + j]) : 0.f;
        if (len > 0) {
            float lgl = (j < LNUM) ? lg[(size_t)(len - 1) * LNUM + j] : SCALE;
            q = __expf(lgl - SCALE) * vstop;
        } else {
            q = vstop;
        }
    }
    if (j < LPAD) {
        q_sh[0][j] = __float2bfloat16(q);
        q_sh[1][j] = __float2bfloat16(0.f);
    }

    // logit addressing: step s reads row (fwd: s) / (bwd: len-2-s)
    const ptrdiff_t strd = bwd ? -(ptrdiff_t)LNUM : (ptrdiff_t)LNUM;
    const ptrdiff_t row0 = bwd ? (ptrdiff_t)(len - 2) * LNUM : 0;
    const float* lgcol = lg + row0 + j;

    float C = 0.f;

    // depth-4 register logit pipeline
    float lgq[4];
    #pragma unroll
    for (int u = 0; u < 4; ++u)
        lgq[u] = (u < nv && j < LNUM) ? lgcol[strd * u] : SCALE;

    __syncthreads();

    for (int tc = 0; tc < n; tc += 4) {
        // prefetch next chunk (MLP=4)
        float lgn[4];
        #pragma unroll
        for (int u = 0; u < 4; ++u) {
            const int sl = tc + 4 + u;
            lgn[u] = (sl < nv && j < LNUM) ? lgcol[strd * sl] : SCALE;
        }

        #pragma unroll
        for (int u = 0; u < 4; ++u) {
            const int t = tc + u;
            if (t >= n) break;                  // uniform across block

            const float el = __expf(lgq[u] - SCALE);
            const bool do_max = ((t & 15) == 0) && (t > 0);

            // y[j] = sum_k E[j,k] * q[k] — 13 LDS.128 + 52 HFMA2 (bf16x2)
            const uint4* ps = reinterpret_cast<const uint4*>(q_sh[t & 1]);
            uint4 v = ps[0];
            bf2 v0 = *reinterpret_cast<bf2*>(&v.x);
            bf2 v1 = *reinterpret_cast<bf2*>(&v.y);
            bf2 v2 = *reinterpret_cast<bf2*>(&v.z);
            bf2 v3 = *reinterpret_cast<bf2*>(&v.w);
            bf2 a0 = __hmul2(E2[0], v0);
            bf2 a1 = __hmul2(E2[1], v1);
            bf2 a2 = __hmul2(E2[2], v2);
            bf2 a3 = __hmul2(E2[3], v3);
            bf2 mx = __hmax2(__hmax2(v0, v1), __hmax2(v2, v3));
            #pragma unroll
            for (int mm = 1; mm < 13; ++mm) {
                uint4 w = ps[mm];
                bf2 w0 = *reinterpret_cast<bf2*>(&w.x);
                bf2 w1 = *reinterpret_cast<bf2*>(&w.y);
                bf2 w2 = *reinterpret_cast<bf2*>(&w.z);
                bf2 w3 = *reinterpret_cast<bf2*>(&w.w);
                a0 = __hfma2(E2[4 * mm + 0], w0, a0);
                a1 = __hfma2(E2[4 * mm + 1], w1, a1);
                a2 = __hfma2(E2[4 * mm + 2], w2, a2);
                a3 = __hfma2(E2[4 * mm + 3], w3, a3);
                if (do_max) {
                    mx = __hmax2(mx, __hmax2(__hmax2(w0, w1), __hmax2(w2, w3)));
                }
            }
            bf2 s2 = __hadd2(__hadd2(a0, a1), __hadd2(a2, a3));
            float y = __low2float(s2) + __high2float(s2);

            if (do_max) {                       // uniform exact renorm every 16 steps
                const float M = fmaxf(
                    fmaxf(__low2float(mx), __high2float(mx)), 1e-30f);
                y *= __fdividef(1.f, M);
                C += __logf(M);
            }

            q = el * y;                         // pads: E2=0 -> y=0 -> q=0
            if (j < LPAD) q_sh[(t + 1) & 1][j] = __float2bfloat16(q);
            __syncthreads();
        }

        #pragma unroll
        for (int u = 0; u < 4; ++u) lgq[u] = lgn[u];
    }

    // publish this half's vector + scale constant
    if (j < LPAD) {
        if (!bwd) g_vecF[b][j] = q;
        else      g_vecB[b][j] = q;
    }
    if (j == 0) {
        const float Ctot = C + SCALE * (float)n;
        if (!bwd) g_CF[b] = Ctot;
        else      g_CB[b] = Ctot;
    }
}

// ---------- combine: out[b] = CF + CB + log( f . g ) ----------
__global__ void combine_kernel(float* __restrict__ out, int B)
{
    const int warp = (blockIdx.x * blockDim.x + threadIdx.x) >> 5;
    const int l    = threadIdx.x & 31;
    if (warp >= B) return;

    double s = 0.0;
    for (int k = l; k < LPAD; k += 32)
        s += (double)g_vecF[warp][k] * (double)g_vecB[warp][k];
    #pragma unroll
    for (int o = 16; o; o >>= 1)
        s += __shfl_xor_sync(0xffffffffu, s, o);
    if (l == 0)
        out[warp] = g_CF[warp] + g_CB[warp] + (float)log(s);
}

extern "C" void kernel_launch(void* const* d_in, const int* in_sizes, int n_in,
                              void* d_out, int out_size)
{
    const float* logits = (const float*)d_in[0];   // [B, T, L] f32
    const float* trans  = (const float*)d_in[1];   // [L, L]    f32
    const int*   lens   = (const int*)d_in[2];     // [B]       i32
    float*       out    = (float*)d_out;           // [B]       f32

    const int B = in_sizes[2];
    const int T = in_sizes[0] / (B * LNUM);

    sort_kernel<<<1, 1024>>>(lens, B, T);
    crf_half_kernel<<<2 * B, NT>>>(logits, trans, lens, T);
    combine_kernel<<<(B * 32 + NT - 1) / NT, NT>>>(out, B);
}